// round 1
// baseline (speedup 1.0000x reference)
#include <cuda_runtime.h>
#include <math.h>

// Problem constants (fixed shapes per dataset)
#define NB     4
#define NPTS   2048          // points per set
#define NTOT   4096          // concat length
#define D      64
#define BM     128           // tile size (points per side)
#define TILES  (NTOT / BM)   // 32
#define LDA    128           // smem row stride (floats)

// Scratch (device globals — no allocation allowed)
__device__ float g_vec[NB][16][D];       // per-slab vector sums
__device__ float g_s1[NB][16];           // per-slab sum of squared norms
__device__ float g_negc[NB];             // -1/(4*bwb) per batch
__device__ float g_part[NB][TILES * TILES];

// ---------------------------------------------------------------------------
// Pass 1a: per-slab stats. grid (16 slabs, 4 batches), 256 threads.
// Slab s covers 256 consecutive points of the concatenated tensor.
// thread t: dim d = t&63, group g = t>>6 handles 64 points.
// ---------------------------------------------------------------------------
__global__ void stats_kernel(const float* __restrict__ x, const float* __restrict__ y) {
    const int s = blockIdx.x;
    const int b = blockIdx.y;
    const int t = threadIdx.x;
    const int d = t & 63;
    const int g = t >> 6;
    const int pbase = s * 256 + g * 64;   // slab of 64 points, single region

    const float* base = (pbase < NPTS)
        ? x + ((size_t)b * NPTS + pbase) * D
        : y + ((size_t)b * NPTS + (pbase - NPTS)) * D;

    float vsum = 0.f, ssum = 0.f;
    #pragma unroll 8
    for (int r = 0; r < 64; ++r) {
        float v = base[(size_t)r * D + d];
        vsum += v;
        ssum = fmaf(v, v, ssum);
    }

    __shared__ float sv[4][64];
    __shared__ float ss[256];
    sv[g][d] = vsum;
    ss[t] = ssum;
    __syncthreads();

    if (t < 64) {
        g_vec[b][s][t] = sv[0][t] + sv[1][t] + sv[2][t] + sv[3][t];
    }
    // tree-reduce ssum over 256 threads (deterministic)
    for (int o = 128; o > 0; o >>= 1) {
        if (t < o) ss[t] += ss[t + o];
        __syncthreads();
    }
    if (t == 0) g_s1[b][s] = ss[0];
}

// ---------------------------------------------------------------------------
// Pass 1b: finalize bandwidth per batch. 1 block, 256 threads.
// sum(L2) = 2*N*S1 - 2*||vec||^2 ;  bwb = sum(L2)/(N^2-N)
// kernel sum uses u = exp(-L2/(4*bwb)) -> u + u^2 + u^4 + u^8 + u^16
// ---------------------------------------------------------------------------
__global__ void finalize_kernel() {
    const int t = threadIdx.x;
    const int b = t >> 6;
    const int d = t & 63;

    float v = 0.f;
    #pragma unroll
    for (int s = 0; s < 16; ++s) v += g_vec[b][s][d];
    float vv = v * v;

    // reduce vv within each 64-thread batch group: warp shuffle + pair combine
    #pragma unroll
    for (int o = 16; o > 0; o >>= 1) vv += __shfl_down_sync(0xffffffffu, vv, o);
    __shared__ float red[8];
    if ((t & 31) == 0) red[t >> 5] = vv;
    __syncthreads();

    if (t < NB) {
        float VV = red[2 * t] + red[2 * t + 1];
        float S1 = 0.f;
        #pragma unroll
        for (int s = 0; s < 16; ++s) S1 += g_s1[t][s];
        float sumL2 = 2.f * (float)NTOT * S1 - 2.f * VV;
        float bwb = sumL2 / (float)((long long)NTOT * NTOT - NTOT);  // 16773120, exact fp32
        g_negc[t] = -1.f / (4.f * bwb);
    }
}

// ---------------------------------------------------------------------------
// Pass 2: fused Gram + Gaussian-kernel-sum over 128x128 pair tiles.
// Only bx <= by computed (symmetry); off-diagonal weighted x2.
// Block sign s_i*s_j is constant per tile (128 | 2048).
// ---------------------------------------------------------------------------
__global__ void __launch_bounds__(256, 2)
mmd_tile_kernel(const float* __restrict__ x, const float* __restrict__ y) {
    const int bx = blockIdx.x, by = blockIdx.y, b = blockIdx.z;
    const int t = threadIdx.x;
    if (bx > by) {
        if (t == 0) g_part[b][by * TILES + bx] = 0.f;
        return;
    }

    extern __shared__ float sm[];
    float* As  = sm;                    // [64][LDA]  (dim-major, transposed)
    float* Bs  = sm + 64 * LDA;         // [64][LDA]
    float* sqA = sm + 2 * 64 * LDA;     // [128]
    float* sqB = sqA + BM;              // [128]

    const float* baseA = (by < 16)
        ? x + ((size_t)b * NPTS + (size_t)by * BM) * D
        : y + ((size_t)b * NPTS + (size_t)(by - 16) * BM) * D;
    const float* baseB = (bx < 16)
        ? x + ((size_t)b * NPTS + (size_t)bx * BM) * D
        : y + ((size_t)b * NPTS + (size_t)(bx - 16) * BM) * D;

    // Load + transpose: warp = one 8-dim group over 32 points (conflict-free STS)
    const int lane_i = t & 31;
    const int w8 = (t >> 5) * 8;
    #pragma unroll
    for (int r = 0; r < 4; ++r) {
        int i = lane_i + r * 32;
        const float* pa = baseA + (size_t)i * D + w8;
        float4 a0 = *(const float4*)pa;
        float4 a1 = *(const float4*)(pa + 4);
        As[(w8 + 0) * LDA + i] = a0.x;
        As[(w8 + 1) * LDA + i] = a0.y;
        As[(w8 + 2) * LDA + i] = a0.z;
        As[(w8 + 3) * LDA + i] = a0.w;
        As[(w8 + 4) * LDA + i] = a1.x;
        As[(w8 + 5) * LDA + i] = a1.y;
        As[(w8 + 6) * LDA + i] = a1.z;
        As[(w8 + 7) * LDA + i] = a1.w;
        const float* pb = baseB + (size_t)i * D + w8;
        float4 b0 = *(const float4*)pb;
        float4 b1 = *(const float4*)(pb + 4);
        Bs[(w8 + 0) * LDA + i] = b0.x;
        Bs[(w8 + 1) * LDA + i] = b0.y;
        Bs[(w8 + 2) * LDA + i] = b0.z;
        Bs[(w8 + 3) * LDA + i] = b0.w;
        Bs[(w8 + 4) * LDA + i] = b1.x;
        Bs[(w8 + 5) * LDA + i] = b1.y;
        Bs[(w8 + 6) * LDA + i] = b1.z;
        Bs[(w8 + 7) * LDA + i] = b1.w;
    }
    __syncthreads();

    // squared norms per point
    if (t < 128) {
        float s = 0.f;
        #pragma unroll 8
        for (int k = 0; k < 64; ++k) { float v = As[k * LDA + t]; s = fmaf(v, v, s); }
        sqA[t] = s;
    } else {
        int j = t - 128;
        float s = 0.f;
        #pragma unroll 8
        for (int k = 0; k < 64; ++k) { float v = Bs[k * LDA + j]; s = fmaf(v, v, s); }
        sqB[j] = s;
    }
    __syncthreads();

    // 8x8 register micro-tile per thread, 16x16 thread grid
    const int tx = t & 15, ty = t >> 4;
    const int i0 = ty * 8, j0 = tx * 8;

    float acc[8][8];
    #pragma unroll
    for (int u = 0; u < 8; ++u)
        #pragma unroll
        for (int v = 0; v < 8; ++v) acc[u][v] = 0.f;

    #pragma unroll 4
    for (int k = 0; k < 64; ++k) {
        float4 a0 = *(const float4*)&As[k * LDA + i0];
        float4 a1 = *(const float4*)&As[k * LDA + i0 + 4];
        float4 b0 = *(const float4*)&Bs[k * LDA + j0];
        float4 b1 = *(const float4*)&Bs[k * LDA + j0 + 4];
        float av[8] = {a0.x, a0.y, a0.z, a0.w, a1.x, a1.y, a1.z, a1.w};
        float bv[8] = {b0.x, b0.y, b0.z, b0.w, b1.x, b1.y, b1.z, b1.w};
        #pragma unroll
        for (int u = 0; u < 8; ++u)
            #pragma unroll
            for (int v = 0; v < 8; ++v)
                acc[u][v] = fmaf(av[u], bv[v], acc[u][v]);
    }

    const float negc = g_negc[b];
    float sA[8], sB[8];
    #pragma unroll
    for (int u = 0; u < 8; ++u) sA[u] = sqA[i0 + u];
    #pragma unroll
    for (int v = 0; v < 8; ++v) sB[v] = sqB[j0 + v];

    float local = 0.f;
    #pragma unroll
    for (int u = 0; u < 8; ++u) {
        #pragma unroll
        for (int v = 0; v < 8; ++v) {
            float l2  = fmaf(-2.f, acc[u][v], sA[u] + sB[v]);
            float e   = __expf(negc * l2);   // u = exp(-L2/(4*bwb))
            float e2  = e * e;
            float e4  = e2 * e2;
            float e8  = e4 * e4;
            float e16 = e8 * e8;
            local += (e + e2) + (e4 + e8) + e16;
        }
    }

    // block reduce (deterministic): warp shuffle + 8-slot smem
    #pragma unroll
    for (int o = 16; o > 0; o >>= 1) local += __shfl_down_sync(0xffffffffu, local, o);
    __shared__ float red[8];
    if ((t & 31) == 0) red[t >> 5] = local;
    __syncthreads();
    if (t == 0) {
        float tot = 0.f;
        #pragma unroll
        for (int w = 0; w < 8; ++w) tot += red[w];
        float sgn = ((by < 16) == (bx < 16)) ? 1.f : -1.f;
        float wt  = (bx == by) ? 1.f : 2.f;
        g_part[b][by * TILES + bx] = tot * sgn * wt;
    }
}

// ---------------------------------------------------------------------------
// Pass 3: reduce per-tile partials -> loss per batch. 4 blocks, 256 threads.
// ---------------------------------------------------------------------------
__global__ void reduce_kernel(float* __restrict__ out) {
    const int b = blockIdx.x;
    const int t = threadIdx.x;
    float s = 0.f;
    #pragma unroll
    for (int idx = t; idx < TILES * TILES; idx += 256) s += g_part[b][idx];
    #pragma unroll
    for (int o = 16; o > 0; o >>= 1) s += __shfl_down_sync(0xffffffffu, s, o);
    __shared__ float red[8];
    if ((t & 31) == 0) red[t >> 5] = s;
    __syncthreads();
    if (t == 0) {
        float tot = 0.f;
        #pragma unroll
        for (int w = 0; w < 8; ++w) tot += red[w];
        out[b] = tot * (1.f / ((float)NPTS * (float)NPTS));
    }
}

extern "C" void kernel_launch(void* const* d_in, const int* in_sizes, int n_in,
                              void* d_out, int out_size) {
    const float* x = (const float*)d_in[0];   // input  (4,2048,64)
    const float* y = (const float*)d_in[1];   // target (4,2048,64)
    float* out = (float*)d_out;               // (4,)

    const int smem_bytes = (2 * 64 * LDA + 2 * BM) * (int)sizeof(float);  // 66560
    cudaFuncSetAttribute(mmd_tile_kernel,
                         cudaFuncAttributeMaxDynamicSharedMemorySize, smem_bytes);

    stats_kernel<<<dim3(16, NB), 256>>>(x, y);
    finalize_kernel<<<1, 256>>>();
    mmd_tile_kernel<<<dim3(TILES, TILES, NB), 256, smem_bytes>>>(x, y);
    reduce_kernel<<<NB, 256>>>(out);
}

// round 4
// speedup vs baseline: 2.5682x; 2.5682x over previous
#include <cuda_runtime.h>
#include <math.h>
#include <stdint.h>

// Problem constants
#define NB     4
#define NPTS   2048
#define NTOT   4096
#define D      64
#define BM     128           // tile side (points)
#define TILES  32
#define NTRI   528           // TILES*(TILES+1)/2
#define STRIDE 68            // smem row stride in floats (conflict-free frag loads)

// Scratch (device globals — no allocation allowed)
__device__ float g_vec[NB][16][D];
__device__ float g_s1[NB][16];
__device__ float g_negc[NB];             // -1/(4*bwb)
__device__ float g_part[NB][NTRI];

__device__ __forceinline__ uint32_t f2tf32(float x) {
    uint32_t r;
    asm("cvt.rna.tf32.f32 %0, %1;" : "=r"(r) : "f"(x));
    return r;
}
__device__ __forceinline__ float ex2f(float x) {
    float r;
    asm("ex2.approx.ftz.f32 %0, %1;" : "=f"(r) : "f"(x));
    return r;
}
__device__ __forceinline__ void mma_tf32(float* c, const uint32_t* a, const uint32_t* bf) {
    asm volatile(
        "mma.sync.aligned.m16n8k8.row.col.f32.tf32.tf32.f32 "
        "{%0,%1,%2,%3}, {%4,%5,%6,%7}, {%8,%9}, {%0,%1,%2,%3};"
        : "+f"(c[0]), "+f"(c[1]), "+f"(c[2]), "+f"(c[3])
        : "r"(a[0]), "r"(a[1]), "r"(a[2]), "r"(a[3]), "r"(bf[0]), "r"(bf[1]));
}

// ---------------------------------------------------------------------------
// Pass 1a: per-slab stats
// ---------------------------------------------------------------------------
__global__ void stats_kernel(const float* __restrict__ x, const float* __restrict__ y) {
    const int s = blockIdx.x, b = blockIdx.y, t = threadIdx.x;
    const int d = t & 63, g = t >> 6;
    const int pbase = s * 256 + g * 64;
    const float* base = (pbase < NPTS)
        ? x + ((size_t)b * NPTS + pbase) * D
        : y + ((size_t)b * NPTS + (pbase - NPTS)) * D;

    float vsum = 0.f, ssum = 0.f;
    #pragma unroll 8
    for (int r = 0; r < 64; ++r) {
        float v = base[(size_t)r * D + d];
        vsum += v;
        ssum = fmaf(v, v, ssum);
    }
    __shared__ float sv[4][64];
    __shared__ float ss[256];
    sv[g][d] = vsum;
    ss[t] = ssum;
    __syncthreads();
    if (t < 64) g_vec[b][s][t] = sv[0][t] + sv[1][t] + sv[2][t] + sv[3][t];
    for (int o = 128; o > 0; o >>= 1) {
        if (t < o) ss[t] += ss[t + o];
        __syncthreads();
    }
    if (t == 0) g_s1[b][s] = ss[0];
}

// ---------------------------------------------------------------------------
// Pass 1b: finalize bandwidth per batch
// ---------------------------------------------------------------------------
__global__ void finalize_kernel() {
    const int t = threadIdx.x;
    const int b = t >> 6, d = t & 63;
    float v = 0.f;
    #pragma unroll
    for (int s = 0; s < 16; ++s) v += g_vec[b][s][d];
    float vv = v * v;
    #pragma unroll
    for (int o = 16; o > 0; o >>= 1) vv += __shfl_down_sync(0xffffffffu, vv, o);
    __shared__ float red[8];
    if ((t & 31) == 0) red[t >> 5] = vv;
    __syncthreads();
    if (t < NB) {
        float VV = red[2 * t] + red[2 * t + 1];
        float S1 = 0.f;
        #pragma unroll
        for (int s = 0; s < 16; ++s) S1 += g_s1[t][s];
        float sumL2 = 2.f * (float)NTOT * S1 - 2.f * VV;
        float bwb = sumL2 / 16773120.f;   // N^2 - N
        g_negc[t] = -1.f / (4.f * bwb);
    }
}

// ---------------------------------------------------------------------------
// Pass 2: tf32 mma.sync Gram + Gaussian-kernel-sum over triangular tiles.
// grid (528, 4), 256 threads (8 warps: 2x4 warp grid, warp tile 64x32).
// ---------------------------------------------------------------------------
__global__ void __launch_bounds__(256, 2)
mmd_tile_kernel(const float* __restrict__ x, const float* __restrict__ y) {
    extern __shared__ float sm[];
    uint32_t* As = (uint32_t*)sm;                     // [128][STRIDE] tf32 bits
    uint32_t* Bs = As + BM * STRIDE;
    float* sqA = (float*)(Bs + BM * STRIDE);          // [128]
    float* sqB = sqA + BM;

    const int t = threadIdx.x;
    const int w = t >> 5, lane = t & 31;
    const int gid = lane >> 2, tig = lane & 3;
    const int b = blockIdx.y;

    // triangular decode: tri -> (by, bx), bx <= by
    const int tri = blockIdx.x;
    int by = (int)((sqrtf(8.f * (float)tri + 1.f) - 1.f) * 0.5f);
    while ((by + 1) * (by + 2) / 2 <= tri) ++by;
    while (by * (by + 1) / 2 > tri) --by;
    const int bx = tri - by * (by + 1) / 2;

    const float* baseA = (by < 16)
        ? x + ((size_t)b * NPTS + (size_t)by * BM) * D
        : y + ((size_t)b * NPTS + (size_t)(by - 16) * BM) * D;
    const float* baseB = (bx < 16)
        ? x + ((size_t)b * NPTS + (size_t)bx * BM) * D
        : y + ((size_t)b * NPTS + (size_t)(bx - 16) * BM) * D;

    // Load tiles, round to tf32, store to smem (row-major, stride 68)
    {
        const int cg = (t & 15) * 4;      // column group
        const int r0 = t >> 4;            // base row
        #pragma unroll
        for (int i = 0; i < 8; ++i) {
            int row = r0 + i * 16;
            float4 a = *(const float4*)(baseA + (size_t)row * D + cg);
            float4 bb = *(const float4*)(baseB + (size_t)row * D + cg);
            uint32_t* pa = As + row * STRIDE + cg;
            pa[0] = f2tf32(a.x);  pa[1] = f2tf32(a.y);
            pa[2] = f2tf32(a.z);  pa[3] = f2tf32(a.w);
            uint32_t* pb = Bs + row * STRIDE + cg;
            pb[0] = f2tf32(bb.x); pb[1] = f2tf32(bb.y);
            pb[2] = f2tf32(bb.z); pb[3] = f2tf32(bb.w);
        }
    }
    __syncthreads();

    // Squared norms from the tf32-rounded values
    {
        int row = t & 127;
        const uint32_t* src = (t < 128) ? As : Bs;
        float s = 0.f;
        #pragma unroll 8
        for (int k = 0; k < 64; ++k) {
            float v = __uint_as_float(src[row * STRIDE + k]);
            s = fmaf(v, v, s);
        }
        if (t < 128) sqA[row] = s; else sqB[row] = s;
    }
    __syncthreads();

    // Warp tile: rows [m0, m0+64), cols [n0, n0+32)
    const int m0 = (w & 1) * 64;
    const int n0 = (w >> 1) * 32;

    float c[4][4][4];
    #pragma unroll
    for (int mf = 0; mf < 4; ++mf)
        #pragma unroll
        for (int nf = 0; nf < 4; ++nf)
            #pragma unroll
            for (int q = 0; q < 4; ++q) c[mf][nf][q] = 0.f;

    #pragma unroll
    for (int ks = 0; ks < 8; ++ks) {
        const int kb = ks * 8;
        uint32_t a[4][4], bf[4][2];
        #pragma unroll
        for (int mf = 0; mf < 4; ++mf) {
            int r = m0 + mf * 16 + gid;
            a[mf][0] = As[r * STRIDE + kb + tig];
            a[mf][1] = As[(r + 8) * STRIDE + kb + tig];
            a[mf][2] = As[r * STRIDE + kb + tig + 4];
            a[mf][3] = As[(r + 8) * STRIDE + kb + tig + 4];
        }
        #pragma unroll
        for (int nf = 0; nf < 4; ++nf) {
            int col = n0 + nf * 8 + gid;
            bf[nf][0] = Bs[col * STRIDE + kb + tig];
            bf[nf][1] = Bs[col * STRIDE + kb + tig + 4];
        }
        #pragma unroll
        for (int mf = 0; mf < 4; ++mf)
            #pragma unroll
            for (int nf = 0; nf < 4; ++nf)
                mma_tf32(c[mf][nf], a[mf], bf[nf]);
    }

    // Epilogue: L2 -> 5-kernel sum via u + u^2 + u^4 + u^8 + u^16
    const float negc2 = g_negc[b] * 1.44269504088896340736f;  // -log2(e)/(4*bwb)
    float local = 0.f;
    #pragma unroll
    for (int mf = 0; mf < 4; ++mf) {
        const int r0i = m0 + mf * 16 + gid;
        const float sA0 = sqA[r0i], sA1 = sqA[r0i + 8];
        #pragma unroll
        for (int nf = 0; nf < 4; ++nf) {
            const int c0i = n0 + nf * 8 + tig * 2;
            const float sB0 = sqB[c0i], sB1 = sqB[c0i + 1];
            const float sAB[4] = {sA0 + sB0, sA0 + sB1, sA1 + sB0, sA1 + sB1};
            #pragma unroll
            for (int q = 0; q < 4; ++q) {
                float l2 = fmaf(-2.f, c[mf][nf][q], sAB[q]);
                float e = ex2f(negc2 * l2);
                float e2 = e * e;
                float e4 = e2 * e2;
                float e8 = e4 * e4;
                float e16 = e8 * e8;
                local += (e + e2) + (e4 + e8) + e16;
            }
        }
    }

    // Block reduce + signed/weighted write
    #pragma unroll
    for (int o = 16; o > 0; o >>= 1) local += __shfl_down_sync(0xffffffffu, local, o);
    __shared__ float red[8];
    if (lane == 0) red[w] = local;
    __syncthreads();
    if (t == 0) {
        float tot = 0.f;
        #pragma unroll
        for (int ww = 0; ww < 8; ++ww) tot += red[ww];
        float sgn = ((by < 16) == (bx < 16)) ? 1.f : -1.f;
        float wt = (bx == by) ? 1.f : 2.f;
        g_part[b][tri] = tot * sgn * wt;
    }
}

// ---------------------------------------------------------------------------
// Pass 3: reduce per-tile partials -> loss per batch
// ---------------------------------------------------------------------------
__global__ void reduce_kernel(float* __restrict__ out) {
    const int b = blockIdx.x, t = threadIdx.x;
    float s = 0.f;
    for (int idx = t; idx < NTRI; idx += 256) s += g_part[b][idx];
    #pragma unroll
    for (int o = 16; o > 0; o >>= 1) s += __shfl_down_sync(0xffffffffu, s, o);
    __shared__ float red[8];
    if ((t & 31) == 0) red[t >> 5] = s;
    __syncthreads();
    if (t == 0) {
        float tot = 0.f;
        #pragma unroll
        for (int w = 0; w < 8; ++w) tot += red[w];
        out[b] = tot * (1.f / ((float)NPTS * (float)NPTS));
    }
}

extern "C" void kernel_launch(void* const* d_in, const int* in_sizes, int n_in,
                              void* d_out, int out_size) {
    const float* x = (const float*)d_in[0];
    const float* y = (const float*)d_in[1];
    float* out = (float*)d_out;

    const int smem_bytes = (2 * BM * STRIDE + 2 * BM) * (int)sizeof(float);  // 70656
    cudaFuncSetAttribute(mmd_tile_kernel,
                         cudaFuncAttributeMaxDynamicSharedMemorySize, smem_bytes);

    stats_kernel<<<dim3(16, NB), 256>>>(x, y);
    finalize_kernel<<<1, 256>>>();
    mmd_tile_kernel<<<dim3(NTRI, NB), 256, smem_bytes>>>(x, y);
    reduce_kernel<<<NB, 256>>>(out);
}